// round 15
// baseline (speedup 1.0000x reference)
#include <cuda_runtime.h>
#include <cuda_bf16.h>
#include <cstdint>

// Problem constants
constexpr int NB  = 2;    // batch
constexpr int NN  = 768;  // nodes
constexpr int NU  = 64;   // embed dim
constexpr int NK  = 8;    // relation dim
constexpr int NIN = 136;  // 2U + K
constexpr int NPD = 160;  // padded hidden (5 per lane * 32 lanes)
constexpr float SLOPE = 0.01f;

// precompute tiling (R7 proven shape)
constexpr int RPB = 4;
constexpr int KH  = 2;
constexpr int PTHREADS = NPD * KH;  // 320
constexpr int PGRID = NB * NN / RPB; // 384

// ---------------- device scratch ----------------
__device__ unsigned char g_mask[NN * NN];
__device__ float g_invD[NN];
__device__ int   g_colcnt[NN];
__device__ int   g_colrows[NN * NN];   // per-column row lists (i-ordered)
__device__ float g_A   [NB * NN * NPD];
__device__ float g_Base[NB * NN * NPD];
__device__ float g_x1  [NB * NN * NU];

// ---------------- shared precompute body ----------------
__device__ __forceinline__ void precompute_body(
    const float* __restrict__ xp,
    const float* __restrict__ W1,
    const float* __restrict__ b1,
    int R0, int tid,
    float (*sx)[NU], float (*spA)[NPD], float (*spB)[NPD])
{
    for (int idx = tid; idx < RPB * NU; idx += PTHREADS)
        sx[idx >> 6][idx & 63] = xp[(size_t)R0 * NU + idx];
    __syncthreads();

    int n  = tid % NPD;
    int kh = tid / NPD;
    float a[RPB], bs[RPB];
    #pragma unroll
    for (int r = 0; r < RPB; r++) { a[r] = 0.0f; bs[r] = 0.0f; }
    if (n < NIN) {
        int ub = kh * 32;
        #pragma unroll 8
        for (int u0 = 0; u0 < 32; u0++) {
            int u = ub + u0;
            float wa = W1[u * NIN + n];
            float wb = W1[(NU + u) * NIN + n];
            #pragma unroll
            for (int r = 0; r < RPB; r++) {
                a[r]  = fmaf(sx[r][u], wa, a[r]);
                bs[r] = fmaf(sx[r][u], wb, bs[r]);
            }
        }
    }
    if (kh == 1) {
        #pragma unroll
        for (int r = 0; r < RPB; r++) { spA[r][n] = a[r]; spB[r][n] = bs[r]; }
    }
    __syncthreads();
    if (kh == 0) {
        float bb = (n < NIN) ? b1[n] : 0.0f;
        #pragma unroll
        for (int r = 0; r < RPB; r++) {
            g_A   [(size_t)(R0 + r) * NPD + n] = a[r] + spA[r][n];
            g_Base[(size_t)(R0 + r) * NPD + n] = bs[r] + spB[r][n] + bb;
        }
    }
}

// ---------------- kernel 1 (fused): pre1 (blocks 0..383) + mask/invD (384..1151) ----------------
__global__ void __launch_bounds__(PTHREADS) fused_pre1_mask_kernel(
    const float* __restrict__ seq,
    const float* __restrict__ rel,
    const float* __restrict__ W1,
    const float* __restrict__ b1)
{
    __shared__ float sx[RPB][NU];
    __shared__ float spA[RPB][NPD];
    __shared__ float spB[RPB][NPD];
    __shared__ int wsum[10];
    int tid = threadIdx.x;

    if (blockIdx.x < PGRID) {
        precompute_body(seq, W1, b1, blockIdx.x * RPB, tid, sx, spA, spB);
        return;
    }

    // mask + row degree + invD for row i
    int i = blockIdx.x - PGRID;
    int cnt = 0;
    for (int j = tid; j < NN; j += PTHREADS) {
        const float4* p = reinterpret_cast<const float4*>(rel + ((size_t)i * NN + j) * NK);
        float4 a = p[0], b = p[1];
        float s = a.x + a.y + a.z + a.w + b.x + b.y + b.z + b.w;
        unsigned char m = (s > 0.0f) ? 1 : 0;
        g_mask[i * NN + j] = m;
        cnt += m;
    }
    #pragma unroll
    for (int o = 16; o > 0; o >>= 1) cnt += __shfl_xor_sync(~0u, cnt, o);
    if ((tid & 31) == 0) wsum[tid >> 5] = cnt;
    __syncthreads();
    if (tid == 0) {
        int t = 0;
        #pragma unroll
        for (int w = 0; w < 10; w++) t += wsum[w];
        g_invD[i] = 1.0f / (float)(t > 0 ? t : 1);
    }
}

// ---------------- kernel 2: per-column lists + counts (ballot compaction) ----------------
__global__ void colbuild_kernel() {
    int j = blockIdx.x;
    int tid = threadIdx.x;          // row i
    int warp = tid >> 5, lane = tid & 31;
    int flag = g_mask[tid * NN + j];
    unsigned bal = __ballot_sync(~0u, flag != 0);
    __shared__ int wcnt[24];
    __shared__ int wpre[25];
    if (lane == 0) wcnt[warp] = __popc(bal);
    __syncthreads();
    if (tid == 0) {
        int acc = 0;
        #pragma unroll
        for (int w = 0; w < 24; w++) { wpre[w] = acc; acc += wcnt[w]; }
        wpre[24] = acc;
        g_colcnt[j] = acc;
    }
    __syncthreads();
    if (flag) {
        int pos = wpre[warp] + __popc(bal & ((1u << lane) - 1u));
        g_colrows[j * NN + pos] = tid;
    }
}

// ---------------- kernel 3: precompute hop 2 ----------------
__global__ void __launch_bounds__(PTHREADS) precompute2_kernel(
    const float* __restrict__ W1,
    const float* __restrict__ b1) {
    __shared__ float sx[RPB][NU];
    __shared__ float spA[RPB][NPD];
    __shared__ float spB[RPB][NPD];
    precompute_body(g_x1, W1, b1, blockIdx.x * RPB, threadIdx.x, sx, spA, spB);
}

// ---------------- kernel 4: edge phase (software-pipelined index prefetch) ----------------
// Block = 1 column x 4 subset warps. Warp sub: 2 edges x 2 batches per iter;
// next iteration's row indices prefetched while current rel/A loads are in flight.
__global__ void __launch_bounds__(128, 5) edge_kernel(
    const float* __restrict__ xin_ext, float* __restrict__ xout_ext,
    int use_g_in, int use_g_out,
    const float* __restrict__ rel,
    const float* __restrict__ W1,      // rows 128..135 = rel weights
    const float* __restrict__ w2,
    const float* __restrict__ b2p)
{
    const float* xin  = use_g_in  ? g_x1 : xin_ext;
    float*       xout = use_g_out ? g_x1 : xout_ext;

    __shared__ float sW1c[NK * NPD];
    __shared__ float sacc[4][2];       // [sub][batch]

    int tid = threadIdx.x, warp = tid >> 5, lane = tid & 31;

    for (int idx = tid; idx < NK * NPD; idx += 128) {
        int kk = idx / NPD, n = idx % NPD;
        sW1c[idx] = (n < NIN) ? W1[(2 * NU + kk) * NIN + n] : 0.0f;
    }
    float w2l[5];
    #pragma unroll
    for (int m = 0; m < 5; m++) {
        int n = lane + 32 * m;
        w2l[m] = (n < NIN) ? w2[n] : 0.0f;
    }
    float b2 = __ldg(b2p);
    __syncthreads();

    int sub = warp;                    // 0..3
    int j   = blockIdx.x;
    int cnt = g_colcnt[j];
    const int* rows = g_colrows + j * NN;

    // hoist Base for (b=0,j) and (b=1,j)
    float base[2][5];
    #pragma unroll
    for (int b = 0; b < 2; b++) {
        const float* Bs = g_Base + ((size_t)(b * NN + j)) * NPD;
        #pragma unroll
        for (int m = 0; m < 5; m++) base[b][m] = Bs[lane + 32 * m];
    }

    float wacc[2] = {0.0f, 0.0f};
    int g = sub;
    int   iv[2];
    float vdv[2];
    if (2 * g < cnt) {       // prologue: load first pair's indices
        #pragma unroll
        for (int s = 0; s < 2; s++) {
            int e = 2 * g + s;
            bool v = (e < cnt);
            int i = rows[v ? e : 0];
            iv[s] = i;
            vdv[s] = v ? g_invD[i] : 0.0f;
        }
    }

    while (2 * g < cnt) {
        // current indices ready: issue rel + A loads immediately
        float rv[2][8];
        #pragma unroll
        for (int s = 0; s < 2; s++) {
            const float4* rp = reinterpret_cast<const float4*>(
                rel + ((size_t)iv[s] * NN + j) * NK);
            float4 r0 = rp[0], r1 = rp[1];
            rv[s][0] = r0.x; rv[s][1] = r0.y; rv[s][2] = r0.z; rv[s][3] = r0.w;
            rv[s][4] = r1.x; rv[s][5] = r1.y; rv[s][6] = r1.z; rv[s][7] = r1.w;
        }
        float av[4][5];     // chain c = s*2 + b
        #pragma unroll
        for (int s = 0; s < 2; s++)
            #pragma unroll
            for (int b = 0; b < 2; b++) {
                const float* Ar = g_A + ((size_t)(b * NN + iv[s])) * NPD;
                #pragma unroll
                for (int m = 0; m < 5; m++)
                    av[s * 2 + b][m] = Ar[lane + 32 * m];
            }

        // prefetch NEXT iteration's indices while loads are in flight
        int gn = g + 4;
        int   niv[2];
        float nvdv[2];
        bool more = (2 * gn < cnt);
        if (more) {
            #pragma unroll
            for (int s = 0; s < 2; s++) {
                int e = 2 * gn + s;
                bool v = (e < cnt);
                int i = rows[v ? e : 0];
                niv[s] = i;
                nvdv[s] = v ? g_invD[i] : 0.0f;
            }
        }

        // rel-term once per EDGE (batch-independent)
        float relc[2][5];
        #pragma unroll
        for (int s = 0; s < 2; s++)
            #pragma unroll
            for (int m = 0; m < 5; m++) relc[s][m] = 0.0f;
        #pragma unroll
        for (int kk = 0; kk < NK; kk++) {
            float w1v[5];
            #pragma unroll
            for (int m = 0; m < 5; m++)
                w1v[m] = sW1c[kk * NPD + lane + 32 * m];
            #pragma unroll
            for (int s = 0; s < 2; s++)
                #pragma unroll
                for (int m = 0; m < 5; m++)
                    relc[s][m] = fmaf(rv[s][kk], w1v[m], relc[s][m]);
        }

        float d[4];
        #pragma unroll
        for (int c = 0; c < 4; c++) {
            int s = c >> 1, b = c & 1;
            float acc = 0.0f;
            #pragma unroll
            for (int m = 0; m < 5; m++) {
                float hv = av[c][m] + (base[b][m] + relc[s][m]);
                hv = fmaxf(hv, SLOPE * hv);
                acc = fmaf(hv, w2l[m], acc);
            }
            d[c] = acc;
        }
        #pragma unroll
        for (int o = 16; o > 0; o >>= 1) {
            #pragma unroll
            for (int c = 0; c < 4; c++)
                d[c] += __shfl_xor_sync(~0u, d[c], o);
        }
        #pragma unroll
        for (int c = 0; c < 4; c++) {
            int s = c >> 1, b = c & 1;
            float o2 = d[c] + b2;
            o2 = fmaxf(o2, SLOPE * o2);
            wacc[b] = fmaf(o2, vdv[s], wacc[b]);
        }

        if (more) {
            iv[0] = niv[0];  iv[1] = niv[1];
            vdv[0] = nvdv[0]; vdv[1] = nvdv[1];
        }
        g = gn;
    }

    if (lane == 0) {
        sacc[sub][0] = wacc[0];
        sacc[sub][1] = wacc[1];
    }
    __syncthreads();

    // warps 0..1 write outputs: warp w -> batch b = w
    if (warp < 2) {
        int b = warp;
        float S = ((sacc[0][b] + sacc[1][b]) + sacc[2][b]) + sacc[3][b];
        size_t obase = ((size_t)(b * NN + j)) * NU;
        xout[obase + lane]      = xin[obase + lane]      * S;
        xout[obase + 32 + lane] = xin[obase + 32 + lane] * S;
    }
}

// ---------------- launch ----------------
extern "C" void kernel_launch(void* const* d_in, const int* in_sizes, int n_in,
                              void* d_out, int out_size) {
    const float* seq  = (const float*)d_in[0];
    const float* rel  = (const float*)d_in[1];
    const float* w1_1 = (const float*)d_in[2];
    const float* b1_1 = (const float*)d_in[3];
    const float* w1_2 = (const float*)d_in[4];
    const float* b1_2 = (const float*)d_in[5];
    const float* w2_1 = (const float*)d_in[6];
    const float* b2_1 = (const float*)d_in[7];
    const float* w2_2 = (const float*)d_in[8];
    const float* b2_2 = (const float*)d_in[9];
    float* out = (float*)d_out;

    // launch 1: pre1 (blocks 0..383) + mask/invD (blocks 384..1151)
    fused_pre1_mask_kernel<<<PGRID + NN, PTHREADS>>>(seq, rel, w1_1, b1_1);
    // launch 2: column lists
    colbuild_kernel<<<NN, 768>>>();
    // launch 3: edge hop 1 (writes g_x1 directly)
    edge_kernel<<<NN, 128>>>(seq, nullptr, 0, 1, rel, w1_1, w1_2, b1_2);
    // launch 4: precompute hop 2 from g_x1
    precompute2_kernel<<<PGRID, PTHREADS>>>(w2_1, b2_1);
    // launch 5: edge hop 2 -> out
    edge_kernel<<<NN, 128>>>(nullptr, out, 1, 0, rel, w2_1, w2_2, b2_2);
}

// round 16
// speedup vs baseline: 1.1223x; 1.1223x over previous
#include <cuda_runtime.h>
#include <cuda_bf16.h>
#include <cstdint>

// Problem constants
constexpr int NB  = 2;    // batch
constexpr int NN  = 768;  // nodes
constexpr int NU  = 64;   // embed dim
constexpr int NK  = 8;    // relation dim
constexpr int NIN = 136;  // 2U + K
constexpr int NPD = 160;  // padded hidden (5 per lane * 32 lanes)
constexpr float SLOPE = 0.01f;

// precompute tiling
constexpr int RPB = 4;
constexpr int KH  = 2;
constexpr int PTHREADS = NPD * KH;   // 320
constexpr int PGRID = NB * NN / RPB; // 384

// ---------------- device scratch ----------------
__device__ unsigned char g_mask[NN * NN];
__device__ float g_invD[NN];
__device__ float g_S[NB * NN];         // hop-1 scale per (b,j)
__device__ int   g_colcnt[NN];
__device__ int   g_colrows[NN * NN];
__device__ float g_A1[NB * NN * NPD];
__device__ float g_B1[NB * NN * NPD];  // includes b1_1 bias
__device__ float g_A2[NB * NN * NPD];  // W2a^T seq (unscaled)
__device__ float g_B2[NB * NN * NPD];  // W2b^T seq (unscaled, NO bias)
__device__ float g_x1[NB * NN * NU];

// ---------------- kernel 1 (fused): quad-GEMM precompute + mask/invD ----------------
__global__ void __launch_bounds__(PTHREADS) fused_pre_kernel(
    const float* __restrict__ seq,
    const float* __restrict__ rel,
    const float* __restrict__ W1,      // hop-1 first linear (136x136)
    const float* __restrict__ b1,      // hop-1 first bias
    const float* __restrict__ W2)      // hop-2 first linear
{
    __shared__ float sx[RPB][NU];
    __shared__ float sp[4][RPB][NPD];
    __shared__ int wsum[10];
    int tid = threadIdx.x;

    if (blockIdx.x < PGRID) {
        int R0 = blockIdx.x * RPB;
        for (int idx = tid; idx < RPB * NU; idx += PTHREADS)
            sx[idx >> 6][idx & 63] = seq[(size_t)R0 * NU + idx];
        __syncthreads();

        int n  = tid % NPD;
        int kh = tid / NPD;
        float a1[RPB], c1[RPB], a2[RPB], c2[RPB];
        #pragma unroll
        for (int r = 0; r < RPB; r++) { a1[r] = c1[r] = a2[r] = c2[r] = 0.0f; }
        if (n < NIN) {
            int ub = kh * 32;
            #pragma unroll 4
            for (int u0 = 0; u0 < 32; u0++) {
                int u = ub + u0;
                float wa1 = W1[u * NIN + n];
                float wb1 = W1[(NU + u) * NIN + n];
                float wa2 = W2[u * NIN + n];
                float wb2 = W2[(NU + u) * NIN + n];
                #pragma unroll
                for (int r = 0; r < RPB; r++) {
                    float xv = sx[r][u];
                    a1[r] = fmaf(xv, wa1, a1[r]);
                    c1[r] = fmaf(xv, wb1, c1[r]);
                    a2[r] = fmaf(xv, wa2, a2[r]);
                    c2[r] = fmaf(xv, wb2, c2[r]);
                }
            }
        }
        if (kh == 1) {
            #pragma unroll
            for (int r = 0; r < RPB; r++) {
                sp[0][r][n] = a1[r]; sp[1][r][n] = c1[r];
                sp[2][r][n] = a2[r]; sp[3][r][n] = c2[r];
            }
        }
        __syncthreads();
        if (kh == 0) {
            float bb = (n < NIN) ? b1[n] : 0.0f;
            #pragma unroll
            for (int r = 0; r < RPB; r++) {
                size_t o = (size_t)(R0 + r) * NPD + n;
                g_A1[o] = a1[r] + sp[0][r][n];
                g_B1[o] = c1[r] + sp[1][r][n] + bb;
                g_A2[o] = a2[r] + sp[2][r][n];
                g_B2[o] = c2[r] + sp[3][r][n];
            }
        }
        return;
    }

    // mask + row degree + invD for row i
    int i = blockIdx.x - PGRID;
    int cnt = 0;
    for (int j = tid; j < NN; j += PTHREADS) {
        const float4* p = reinterpret_cast<const float4*>(rel + ((size_t)i * NN + j) * NK);
        float4 a = p[0], b = p[1];
        float s = a.x + a.y + a.z + a.w + b.x + b.y + b.z + b.w;
        unsigned char m = (s > 0.0f) ? 1 : 0;
        g_mask[i * NN + j] = m;
        cnt += m;
    }
    #pragma unroll
    for (int o = 16; o > 0; o >>= 1) cnt += __shfl_xor_sync(~0u, cnt, o);
    if ((tid & 31) == 0) wsum[tid >> 5] = cnt;
    __syncthreads();
    if (tid == 0) {
        int t = 0;
        #pragma unroll
        for (int w = 0; w < 10; w++) t += wsum[w];
        g_invD[i] = 1.0f / (float)(t > 0 ? t : 1);
    }
}

// ---------------- kernel 2: per-column lists + counts ----------------
__global__ void colbuild_kernel() {
    int j = blockIdx.x;
    int tid = threadIdx.x;          // row i
    int warp = tid >> 5, lane = tid & 31;
    int flag = g_mask[tid * NN + j];
    unsigned bal = __ballot_sync(~0u, flag != 0);
    __shared__ int wcnt[24];
    __shared__ int wpre[25];
    if (lane == 0) wcnt[warp] = __popc(bal);
    __syncthreads();
    if (tid == 0) {
        int acc = 0;
        #pragma unroll
        for (int w = 0; w < 24; w++) { wpre[w] = acc; acc += wcnt[w]; }
        wpre[24] = acc;
        g_colcnt[j] = acc;
    }
    __syncthreads();
    if (flag) {
        int pos = wpre[warp] + __popc(bal & ((1u << lane) - 1u));
        g_colrows[j * NN + pos] = tid;
    }
}

// ---------------- kernel 3: edge phase (templated on hop) ----------------
// HOP2=0: A=g_A1, base=g_B1 (bias baked), h = A + base + relc
// HOP2=1: A=g_A2 scaled by S_i, base = S_j*g_B2 + bias1, h = fma(S_i, A, base+relc)
template <int HOP2>
__global__ void __launch_bounds__(128, 6) edge_kernel(
    const float* __restrict__ xin_ext, float* __restrict__ xout_ext,
    int use_g_in, int use_g_out,
    const float* __restrict__ rel,
    const float* __restrict__ W1,      // rows 128..135 = rel weights (this hop)
    const float* __restrict__ bias1,   // first-linear bias (HOP2 only)
    const float* __restrict__ w2,
    const float* __restrict__ b2p)
{
    const float* xin  = use_g_in  ? g_x1 : xin_ext;
    float*       xout = use_g_out ? g_x1 : xout_ext;
    const float* Amat = HOP2 ? g_A2 : g_A1;

    __shared__ float sW1c[NK * NPD];
    __shared__ float sacc[4][2];       // [sub][batch]

    int tid = threadIdx.x, warp = tid >> 5, lane = tid & 31;

    for (int idx = tid; idx < NK * NPD; idx += 128) {
        int kk = idx / NPD, n = idx % NPD;
        sW1c[idx] = (n < NIN) ? W1[(2 * NU + kk) * NIN + n] : 0.0f;
    }
    float w2l[5];
    #pragma unroll
    for (int m = 0; m < 5; m++) {
        int n = lane + 32 * m;
        w2l[m] = (n < NIN) ? w2[n] : 0.0f;
    }
    float b2 = __ldg(b2p);
    __syncthreads();

    int sub = warp;                    // 0..3
    int j   = blockIdx.x;
    int cnt = g_colcnt[j];
    const int* rows = g_colrows + j * NN;

    // hoist base for (b=0,j) and (b=1,j)
    float base[2][5];
    #pragma unroll
    for (int b = 0; b < 2; b++) {
        if (HOP2) {
            float Sj = g_S[b * NN + j];
            const float* Bs = g_B2 + ((size_t)(b * NN + j)) * NPD;
            #pragma unroll
            for (int m = 0; m < 5; m++) {
                int n = lane + 32 * m;
                float bb = (n < NIN) ? bias1[n] : 0.0f;
                base[b][m] = fmaf(Sj, Bs[n], bb);
            }
        } else {
            const float* Bs = g_B1 + ((size_t)(b * NN + j)) * NPD;
            #pragma unroll
            for (int m = 0; m < 5; m++) base[b][m] = Bs[lane + 32 * m];
        }
    }

    float wacc[2] = {0.0f, 0.0f};
    for (int g = sub; 2 * g < cnt; g += 4) {
        int e0 = 2 * g;
        float vdv[2];
        float rv[2][8];
        float av[4][5];     // chain c = s*2 + b
        float Sv[4];        // HOP2: S[b,i] per chain
        int iv[2];

        #pragma unroll
        for (int s = 0; s < 2; s++) {
            int e = e0 + s;
            bool v = (e < cnt);
            int i = rows[v ? e : 0];
            iv[s] = i;
            vdv[s] = v ? g_invD[i] : 0.0f;
            const float4* rp = reinterpret_cast<const float4*>(
                rel + ((size_t)i * NN + j) * NK);
            float4 r0 = rp[0], r1 = rp[1];
            rv[s][0] = r0.x; rv[s][1] = r0.y; rv[s][2] = r0.z; rv[s][3] = r0.w;
            rv[s][4] = r1.x; rv[s][5] = r1.y; rv[s][6] = r1.z; rv[s][7] = r1.w;
        }
        #pragma unroll
        for (int s = 0; s < 2; s++)
            #pragma unroll
            for (int b = 0; b < 2; b++) {
                const float* Ar = Amat + ((size_t)(b * NN + iv[s])) * NPD;
                #pragma unroll
                for (int m = 0; m < 5; m++)
                    av[s * 2 + b][m] = Ar[lane + 32 * m];
                if (HOP2) Sv[s * 2 + b] = g_S[b * NN + iv[s]];
            }

        // rel-term once per EDGE (batch-independent)
        float relc[2][5];
        #pragma unroll
        for (int s = 0; s < 2; s++)
            #pragma unroll
            for (int m = 0; m < 5; m++) relc[s][m] = 0.0f;
        #pragma unroll
        for (int kk = 0; kk < NK; kk++) {
            float w1v[5];
            #pragma unroll
            for (int m = 0; m < 5; m++)
                w1v[m] = sW1c[kk * NPD + lane + 32 * m];
            #pragma unroll
            for (int s = 0; s < 2; s++)
                #pragma unroll
                for (int m = 0; m < 5; m++)
                    relc[s][m] = fmaf(rv[s][kk], w1v[m], relc[s][m]);
        }

        float d[4];
        #pragma unroll
        for (int c = 0; c < 4; c++) {
            int s = c >> 1, b = c & 1;
            float acc = 0.0f;
            #pragma unroll
            for (int m = 0; m < 5; m++) {
                float hv;
                if (HOP2) hv = fmaf(Sv[c], av[c][m], base[b][m] + relc[s][m]);
                else      hv = av[c][m] + (base[b][m] + relc[s][m]);
                hv = fmaxf(hv, SLOPE * hv);
                acc = fmaf(hv, w2l[m], acc);
            }
            d[c] = acc;
        }
        #pragma unroll
        for (int o = 16; o > 0; o >>= 1) {
            #pragma unroll
            for (int c = 0; c < 4; c++)
                d[c] += __shfl_xor_sync(~0u, d[c], o);
        }
        #pragma unroll
        for (int c = 0; c < 4; c++) {
            int s = c >> 1, b = c & 1;
            float o2 = d[c] + b2;
            o2 = fmaxf(o2, SLOPE * o2);
            wacc[b] = fmaf(o2, vdv[s], wacc[b]);
        }
    }

    if (lane == 0) {
        sacc[sub][0] = wacc[0];
        sacc[sub][1] = wacc[1];
    }
    __syncthreads();

    // warps 0..1 write outputs (and store S for hop 1)
    if (warp < 2) {
        int b = warp;
        float S = ((sacc[0][b] + sacc[1][b]) + sacc[2][b]) + sacc[3][b];
        if (!HOP2 && lane == 0) g_S[b * NN + j] = S;
        size_t obase = ((size_t)(b * NN + j)) * NU;
        xout[obase + lane]      = xin[obase + lane]      * S;
        xout[obase + 32 + lane] = xin[obase + 32 + lane] * S;
    }
}

// ---------------- launch ----------------
extern "C" void kernel_launch(void* const* d_in, const int* in_sizes, int n_in,
                              void* d_out, int out_size) {
    const float* seq  = (const float*)d_in[0];
    const float* rel  = (const float*)d_in[1];
    const float* w1_1 = (const float*)d_in[2];
    const float* b1_1 = (const float*)d_in[3];
    const float* w1_2 = (const float*)d_in[4];
    const float* b1_2 = (const float*)d_in[5];
    const float* w2_1 = (const float*)d_in[6];
    const float* b2_1 = (const float*)d_in[7];
    const float* w2_2 = (const float*)d_in[8];
    const float* b2_2 = (const float*)d_in[9];
    float* out = (float*)d_out;

    // launch 1: quad-GEMM precompute (blocks 0..383) + mask/invD (384..1151)
    fused_pre_kernel<<<PGRID + NN, PTHREADS>>>(seq, rel, w1_1, b1_1, w2_1);
    // launch 2: column lists
    colbuild_kernel<<<NN, 768>>>();
    // launch 3: edge hop 1 -> g_x1 + g_S
    edge_kernel<0><<<NN, 128>>>(seq, nullptr, 0, 1, rel, w1_1, nullptr, w1_2, b1_2);
    // launch 4: edge hop 2 -> out (A2/B2 scaled by S on the fly)
    edge_kernel<1><<<NN, 128>>>(nullptr, out, 1, 0, rel, w2_1, b2_1, w2_2, b2_2);
}